// round 1
// baseline (speedup 1.0000x reference)
#include <cuda_runtime.h>
#include <cstdint>

#define B 16
#define S 4096
#define E 2048
#define WIN 64
#define ROWS (B * S)

// Scratch for masked scores s[b,s] (device global: no allocation allowed)
__device__ float g_scores[ROWS];

// Kernel 1: one block per row. 256 threads x 2 float4 = 2048 floats.
__global__ __launch_bounds__(256) void dot_kernel(
    const float* __restrict__ x,
    const int*   __restrict__ mask,   // works for int32 {0,1} or float32 {0.0,1.0} bit patterns
    const float* __restrict__ W,
    const float* __restrict__ bias)
{
    const int row = blockIdx.x;
    const int t   = threadIdx.x;

    const float4* __restrict__ xr = reinterpret_cast<const float4*>(x) + (size_t)row * (E / 4);
    const float4* __restrict__ Wv = reinterpret_cast<const float4*>(W);

    // Issue all 4 loads up front (x misses to HBM; W hits L1 after warmup)
    float4 a0 = xr[t];
    float4 a1 = xr[t + 256];
    float4 w0 = Wv[t];
    float4 w1 = Wv[t + 256];

    float sum = a0.x * w0.x + a0.y * w0.y + a0.z * w0.z + a0.w * w0.w
              + a1.x * w1.x + a1.y * w1.y + a1.z * w1.z + a1.w * w1.w;

    // warp reduce
    #pragma unroll
    for (int o = 16; o > 0; o >>= 1)
        sum += __shfl_xor_sync(0xFFFFFFFFu, sum, o);

    __shared__ float part[8];
    if ((t & 31) == 0) part[t >> 5] = sum;
    __syncthreads();

    if (t == 0) {
        float tot = part[0] + part[1] + part[2] + part[3]
                  + part[4] + part[5] + part[6] + part[7] + bias[0];
        g_scores[row] = (mask[row] != 0) ? tot : 0.0f;
    }
}

// Kernel 2: one block per batch. Window sums + max.
__global__ __launch_bounds__(256) void window_kernel(float* __restrict__ out)
{
    const int b = blockIdx.x;
    const int t = threadIdx.x;

    __shared__ float s[S];
    const float* __restrict__ src = g_scores + (size_t)b * S;
    for (int i = t; i < S; i += 256) s[i] = src[i];
    __syncthreads();

    const int nwin = S - WIN + 1;  // 4033
    float best = -3.4e38f;
    for (int w = t; w < nwin; w += 256) {
        float acc = 0.0f;
        #pragma unroll
        for (int k = 0; k < WIN; k++) acc += s[w + k];
        best = fmaxf(best, acc);
    }

    // block max reduce
    #pragma unroll
    for (int o = 16; o > 0; o >>= 1)
        best = fmaxf(best, __shfl_xor_sync(0xFFFFFFFFu, best, o));

    __shared__ float pm[8];
    if ((t & 31) == 0) pm[t >> 5] = best;
    __syncthreads();
    if (t == 0) {
        float m = pm[0];
        #pragma unroll
        for (int i = 1; i < 8; i++) m = fmaxf(m, pm[i]);
        out[b] = m / (float)WIN;
    }
}

extern "C" void kernel_launch(void* const* d_in, const int* in_sizes, int n_in,
                              void* d_out, int out_size)
{
    const float* x    = (const float*)d_in[0];
    const int*   mask = (const int*)  d_in[1];
    const float* W    = (const float*)d_in[2];
    const float* bias = (const float*)d_in[3];
    float*       out  = (float*)d_out;

    dot_kernel<<<ROWS, 256>>>(x, mask, W, bias);
    window_kernel<<<B, 256>>>(out);
}

// round 3
// speedup vs baseline: 1.2749x; 1.2749x over previous
#include <cuda_runtime.h>
#include <cstdint>

#define B 16
#define S 4096
#define E 2048
#define WIN 64
#define ROWS (B * S)

#define CHUNKS 16        // window chunks per batch
#define WPB 256          // windows per block (kernel 2)
#define NWIN (S - WIN + 1)   // 4033

__device__ float g_scores[ROWS];
__device__ float g_part[B * CHUNKS];

// ---------------------------------------------------------------------------
// Kernel 1: one WARP per row. thread t loads float4 at t + 32*i, i=0..15.
// MLP=16 outstanding HBM loads per thread; no block-level sync needed.
// ---------------------------------------------------------------------------
__global__ __launch_bounds__(256) void dot_kernel(
    const float* __restrict__ x,
    const int*   __restrict__ mask,   // int32 {0,1} or float32 {0.,1.} bit patterns
    const float* __restrict__ W,
    const float* __restrict__ bias)
{
    const int warp = (blockIdx.x * blockDim.x + threadIdx.x) >> 5;  // row id
    const int lane = threadIdx.x & 31;
    if (warp >= ROWS) return;

    const float4* __restrict__ xr = reinterpret_cast<const float4*>(x) + (size_t)warp * (E / 4);
    const float4* __restrict__ Wv = reinterpret_cast<const float4*>(W);

    float s0 = 0.f, s1 = 0.f, s2 = 0.f, s3 = 0.f;
    #pragma unroll
    for (int i = 0; i < 16; i += 4) {
        float4 a0 = xr[lane + (i + 0) * 32];
        float4 a1 = xr[lane + (i + 1) * 32];
        float4 a2 = xr[lane + (i + 2) * 32];
        float4 a3 = xr[lane + (i + 3) * 32];
        float4 w0 = Wv[lane + (i + 0) * 32];
        float4 w1 = Wv[lane + (i + 1) * 32];
        float4 w2 = Wv[lane + (i + 2) * 32];
        float4 w3 = Wv[lane + (i + 3) * 32];
        s0 += a0.x * w0.x + a0.y * w0.y + a0.z * w0.z + a0.w * w0.w;
        s1 += a1.x * w1.x + a1.y * w1.y + a1.z * w1.z + a1.w * w1.w;
        s2 += a2.x * w2.x + a2.y * w2.y + a2.z * w2.z + a2.w * w2.w;
        s3 += a3.x * w3.x + a3.y * w3.y + a3.z * w3.z + a3.w * w3.w;
    }
    float sum = (s0 + s1) + (s2 + s3);

    #pragma unroll
    for (int o = 16; o > 0; o >>= 1)
        sum += __shfl_xor_sync(0xFFFFFFFFu, sum, o);

    if (lane == 0) {
        float tot = sum + bias[0];
        g_scores[warp] = (mask[warp] != 0) ? tot : 0.0f;
    }
}

// ---------------------------------------------------------------------------
// Kernel 2: grid = (CHUNKS, B). Each block covers WPB=256 window starts.
// Stages WPB+WIN-1 scores in smem; thread t sums its 64-wide window
// (consecutive lanes -> consecutive smem addrs -> conflict-free).
// ---------------------------------------------------------------------------
__global__ __launch_bounds__(256) void window_kernel()
{
    const int chunk = blockIdx.x;
    const int b     = blockIdx.y;
    const int t     = threadIdx.x;
    const int base  = chunk * WPB;

    __shared__ float sm[WPB + WIN - 1];   // 319
    const float* __restrict__ src = g_scores + (size_t)b * S;

    for (int i = t; i < WPB + WIN - 1; i += 256) {
        int idx = base + i;
        sm[i] = (idx < S) ? src[idx] : 0.0f;
    }
    __syncthreads();

    float best = -3.4e38f;
    const int w = base + t;
    if (w < NWIN) {
        float acc = 0.0f;
        #pragma unroll
        for (int k = 0; k < WIN; k++) acc += sm[t + k];
        best = acc;
    }

    #pragma unroll
    for (int o = 16; o > 0; o >>= 1)
        best = fmaxf(best, __shfl_xor_sync(0xFFFFFFFFu, best, o));

    __shared__ float pm[8];
    if ((t & 31) == 0) pm[t >> 5] = best;
    __syncthreads();
    if (t == 0) {
        float m = pm[0];
        #pragma unroll
        for (int i = 1; i < 8; i++) m = fmaxf(m, pm[i]);
        g_part[b * CHUNKS + chunk] = m;
    }
}

// ---------------------------------------------------------------------------
// Kernel 3: single tiny block reduces partials -> out[B], divides by WIN.
// ---------------------------------------------------------------------------
__global__ void final_kernel(float* __restrict__ out)
{
    const int t = threadIdx.x;
    if (t < B) {
        float m = -3.4e38f;
        #pragma unroll
        for (int c = 0; c < CHUNKS; c++)
            m = fmaxf(m, g_part[t * CHUNKS + c]);
        out[t] = m / (float)WIN;
    }
}

extern "C" void kernel_launch(void* const* d_in, const int* in_sizes, int n_in,
                              void* d_out, int out_size)
{
    const float* x    = (const float*)d_in[0];
    const int*   mask = (const int*)  d_in[1];
    const float* W    = (const float*)d_in[2];
    const float* bias = (const float*)d_in[3];
    float*       out  = (float*)d_out;

    dot_kernel<<<ROWS / 8, 256>>>(x, mask, W, bias);   // 8 warps/block, 1 row/warp
    window_kernel<<<dim3(CHUNKS, B), 256>>>();
    final_kernel<<<1, 32>>>(out);
}